// round 3
// baseline (speedup 1.0000x reference)
#include <cuda_runtime.h>
#include <cuda_bf16.h>

// Problem: for each of M molecules, S = 32x128 fp32 rows; C = S S^T (32x32),
// output smallest eigenvalue of C.  One warp per molecule:
//   1) Gram via SMEM-staged chunks (fp32)
//   2) Householder tridiagonalization (warp-cooperative, lane = row)
//   3) 32-way multisection bisection on the Sturm sequence (lane = shift)

#define NA 32
#define NF 128
#define WPB 4   // warps (=molecules) per block

__global__ void __launch_bounds__(32 * WPB, 1)
corr_minEig_kernel(const float* __restrict__ S, float* __restrict__ out, int mtot) {
    __shared__ __align__(16) float sS[WPB][NA * 36];  // staging, stride 36 (16B-aligned rows)
    __shared__ float sA[WPB][NA * 33];                // C / Householder workspace, stride 33
    __shared__ float sv[WPB][NA];
    __shared__ float swv[WPB][NA];
    __shared__ float sd[WPB][NA];
    __shared__ float se2[WPB][NA];

    const int w    = threadIdx.x >> 5;
    const int lane = threadIdx.x & 31;
    const int mol  = blockIdx.x * WPB + w;
    if (mol >= mtot) return;

    const float* Sm = S + (size_t)mol * NA * NF;
    float* A_ = sA[w];
    float* v  = sv[w];
    float* ww = swv[w];
    float* d  = sd[w];
    float* e2 = se2[w];

    // ------------------------------------------------------------------
    // 1) Gram: C[l][j] = dot(row l, row j), chunked over k in blocks of 32
    // ------------------------------------------------------------------
    float acc[NA];
#pragma unroll
    for (int j = 0; j < NA; j++) acc[j] = 0.f;

    for (int kc = 0; kc < NF; kc += 32) {
        // stage 32x32 chunk (coalesced: 4 rows x 8 lanes of float4 per iter)
#pragma unroll
        for (int it = 0; it < 8; it++) {
            int p   = it * 32 + lane;   // 0..255 float4 slots
            int row = p >> 3;
            int c4  = p & 7;
            float4 x = *(const float4*)(Sm + row * NF + kc + c4 * 4);
            *(float4*)(&sS[w][row * 36 + c4 * 4]) = x;
        }
        __syncwarp();

        // own row chunk into registers
        float4 a[8];
#pragma unroll
        for (int c4 = 0; c4 < 8; c4++) a[c4] = *(const float4*)(&sS[w][lane * 36 + c4 * 4]);

        // accumulate against broadcast row j
#pragma unroll
        for (int j = 0; j < NA; j++) {
            float s0 = 0.f, s1 = 0.f, s2 = 0.f, s3 = 0.f;
#pragma unroll
            for (int c4 = 0; c4 < 8; c4++) {
                float4 b = *(const float4*)(&sS[w][j * 36 + c4 * 4]);
                s0 += a[c4].x * b.x;
                s1 += a[c4].y * b.y;
                s2 += a[c4].z * b.z;
                s3 += a[c4].w * b.w;
            }
            acc[j] += (s0 + s1) + (s2 + s3);
        }
        __syncwarp();
    }

    // write C row (lane l owns row l); stride 33 -> conflict-free
#pragma unroll
    for (int j = 0; j < NA; j++) A_[lane * 33 + j] = acc[j];
    __syncwarp();

    // ------------------------------------------------------------------
    // 2) Householder tridiagonalization (lane r owns row r)
    // ------------------------------------------------------------------
    for (int k = 0; k < NA - 2; k++) {
        float xr = (lane > k) ? A_[lane * 33 + k] : 0.f;
        float x0 = __shfl_sync(0xffffffffu, xr, k + 1);
        float sig = (lane > k + 1) ? xr * xr : 0.f;
#pragma unroll
        for (int o = 16; o; o >>= 1) sig += __shfl_xor_sync(0xffffffffu, sig, o);

        float alpha, vr = 0.f, beta = 0.f;
        if (sig < 1e-30f) {
            alpha = x0;                      // already tridiagonal in this column
        } else {
            float mu = sqrtf(x0 * x0 + sig);
            alpha = (x0 > 0.f) ? -mu : mu;
            float v0 = x0 - alpha;
            vr = (lane == k + 1) ? v0 : ((lane > k + 1) ? xr : 0.f);
            beta = 2.f / (v0 * v0 + sig);
        }
        if (lane == k) {
            d[k]      = A_[k * 33 + k];
            e2[k + 1] = alpha * alpha;
        }
        v[lane] = vr;
        __syncwarp();

        if (beta > 0.f) {                    // uniform across warp
            // p = beta * A v on trailing submatrix
            float p = 0.f;
            if (lane > k) {
                for (int c = k + 1; c < NA; c++) p += A_[lane * 33 + c] * v[c];
                p *= beta;
            }
            float pv = p * vr;
#pragma unroll
            for (int o = 16; o; o >>= 1) pv += __shfl_xor_sync(0xffffffffu, pv, o);
            float K  = 0.5f * beta * pv;
            float wr = p - K * vr;
            ww[lane] = wr;
            __syncwarp();
            if (lane > k) {
                for (int c = k + 1; c < NA; c++)
                    A_[lane * 33 + c] -= vr * ww[c] + wr * v[c];
            }
        }
        __syncwarp();
    }
    if (lane == 0) {
        d[NA - 2] = A_[(NA - 2) * 33 + (NA - 2)];
        d[NA - 1] = A_[(NA - 1) * 33 + (NA - 1)];
        float e31 = A_[(NA - 1) * 33 + (NA - 2)];
        e2[NA - 1] = e31 * e31;
        e2[0] = 0.f;
    }
    __syncwarp();

    // ------------------------------------------------------------------
    // 3) Smallest eigenvalue: Gershgorin bracket + 32-way multisection
    //    using the Sturm sequence count (#eigs < x) per lane shift.
    // ------------------------------------------------------------------
    float ei  = sqrtf(e2[lane]);
    float eip = (lane < NA - 1) ? sqrtf(e2[lane + 1]) : 0.f;
    float rad = ei + eip;
    float dl  = d[lane];
    float lo = dl - rad, hi = dl + rad;
#pragma unroll
    for (int o = 16; o; o >>= 1) {
        lo = fminf(lo, __shfl_xor_sync(0xffffffffu, lo, o));
        hi = fmaxf(hi, __shfl_xor_sync(0xffffffffu, hi, o));
    }

    for (int it = 0; it < 6; it++) {
        float step = (hi - lo) * (1.f / 33.f);
        float x = lo + step * (float)(lane + 1);
        int cnt = 0;
        float q = d[0] - x;
        if (q < 0.f) cnt++;
        for (int i = 1; i < NA; i++) {
            if (fabsf(q) < 1e-25f) q = (q < 0.f) ? -1e-25f : 1e-25f;
            q = (d[i] - x) - e2[i] / q;
            if (q < 0.f) cnt++;
        }
        unsigned mask = __ballot_sync(0xffffffffu, cnt >= 1);
        if (mask == 0u) {
            lo = lo + step * 32.f;           // lambda_min above all probes
        } else {
            int idx = __ffs(mask) - 1;       // first probe with an eig below it
            hi = lo + step * (float)(idx + 1);
            lo = lo + step * (float)idx;
        }
    }

    if (lane == 0) out[mol] = 0.5f * (lo + hi);
}

extern "C" void kernel_launch(void* const* d_in, const int* in_sizes, int n_in,
                              void* d_out, int out_size) {
    const float* sr = (const float*)d_in[0];   // [M*32, 128] fp32
    // d_in[1] = idx_m (int32) — uniform groups, unused
    float* out = (float*)d_out;

    int n_atoms = in_sizes[0] / NF;
    int mtot    = n_atoms / NA;                // 8192

    int blocks = (mtot + WPB - 1) / WPB;
    corr_minEig_kernel<<<blocks, 32 * WPB>>>(sr, out, mtot);
}

// round 7
// speedup vs baseline: 2.3180x; 2.3180x over previous
#include <cuda_runtime.h>
#include <cuda_bf16.h>
#include <cstdint>

// Per molecule: S = 32x128 fp32, C = S S^T (32x32), output lambda_min(C).
// One warp per molecule:
//   1) Gram via SMEM-staged 32x32 chunks, packed f32x2 FMA (FFMA2)
//   2) Householder tridiagonalization with the A-row resident in registers
//      (16 packed b64 per lane); column k recovered from row k by symmetry.
//   3) lambda_min via 32-way multisection on the Sturm sequence.

#define NA 32
#define NF 128
#define WPB 4   // warps (=molecules) per block

typedef unsigned long long u64;

__device__ __forceinline__ u64 pk2(float x, float y) {
    u64 r; asm("mov.b64 %0, {%1,%2};" : "=l"(r) : "f"(x), "f"(y)); return r;
}
__device__ __forceinline__ void upk2(u64 v, float& x, float& y) {
    asm("mov.b64 {%0,%1}, %2;" : "=f"(x), "=f"(y) : "l"(v));
}
__device__ __forceinline__ u64 ffma2(u64 a, u64 b, u64 c) {
    u64 d; asm("fma.rn.f32x2 %0, %1, %2, %3;" : "=l"(d) : "l"(a), "l"(b), "l"(c)); return d;
}
__device__ __forceinline__ u64 fadd2(u64 a, u64 b) {
    u64 d; asm("add.rn.f32x2 %0, %1, %2;" : "=l"(d) : "l"(a), "l"(b)); return d;
}
__device__ __forceinline__ void lds_v2u64(uint32_t addr, u64& a, u64& b) {
    asm("ld.shared.v2.b64 {%0,%1}, [%2];" : "=l"(a), "=l"(b) : "r"(addr));
}
__device__ __forceinline__ u64 lds_u64(uint32_t addr) {
    u64 a; asm("ld.shared.b64 %0, [%1];" : "=l"(a) : "r"(addr)); return a;
}
__device__ __forceinline__ void sts_u64(uint32_t addr, u64 v) {
    asm volatile("st.shared.b64 [%0], %1;" :: "r"(addr), "l"(v) : "memory");
}

__global__ void __launch_bounds__(32 * WPB, 4)
corr_minEig_kernel(const float* __restrict__ S, float* __restrict__ out, int mtot) {
    __shared__ __align__(16) float sS[WPB][NA * 36];   // 32x32 chunk staging, stride 36
    __shared__ __align__(16) float scol[WPB][NA];      // row-k spill (== column k by symmetry)
    __shared__ __align__(16) float sv[WPB][NA];        // Householder v
    __shared__ __align__(16) float sw[WPB][NA];        // Householder w
    __shared__ float sd[WPB][NA];                      // tridiagonal diag
    __shared__ float se2[WPB][NA];                     // tridiagonal offdiag^2

    const int w    = threadIdx.x >> 5;
    const int lane = threadIdx.x & 31;
    const int mol  = blockIdx.x * WPB + w;
    if (mol >= mtot) return;

    const float* Sm = S + (size_t)mol * NA * NF;
    const uint32_t sS_base  = (uint32_t)__cvta_generic_to_shared(&sS[w][0]);
    const uint32_t v_base   = (uint32_t)__cvta_generic_to_shared(&sv[w][0]);
    const uint32_t w_base   = (uint32_t)__cvta_generic_to_shared(&sw[w][0]);
    const uint32_t col_base = (uint32_t)__cvta_generic_to_shared(&scol[w][0]);
    float* d  = sd[w];
    float* e2 = se2[w];

    // ------------------------------------------------------------------
    // 1) Gram: acc[j] = dot(row lane, row j), chunked over k, packed FMA
    // ------------------------------------------------------------------
    float acc[NA];
#pragma unroll
    for (int j = 0; j < NA; j++) acc[j] = 0.f;

    for (int kc = 0; kc < NF; kc += 32) {
        // stage 32x32 chunk (coalesced 128B segments)
#pragma unroll
        for (int it = 0; it < 8; it++) {
            int p   = it * 32 + lane;
            int row = p >> 3;
            int c4  = p & 7;
            float4 x = *(const float4*)(Sm + row * NF + kc + c4 * 4);
            *(float4*)(&sS[w][row * 36 + c4 * 4]) = x;
        }
        __syncwarp();

        // own row chunk -> 16 packed b64 (conflict-free: stride-36 rows, 8-lane phases)
        u64 a2[16];
#pragma unroll
        for (int c4 = 0; c4 < 8; c4++)
            lds_v2u64(sS_base + (uint32_t)(lane * 36 + c4 * 4) * 4, a2[2 * c4], a2[2 * c4 + 1]);

#pragma unroll
        for (int j = 0; j < NA; j++) {
            u64 s01 = 0, s23 = 0;
#pragma unroll
            for (int c4 = 0; c4 < 8; c4++) {
                u64 b01, b23;   // broadcast load
                lds_v2u64(sS_base + (uint32_t)(j * 36 + c4 * 4) * 4, b01, b23);
                s01 = ffma2(a2[2 * c4],     b01, s01);
                s23 = ffma2(a2[2 * c4 + 1], b23, s23);
            }
            u64 s = fadd2(s01, s23);
            float lo, hi; upk2(s, lo, hi);
            acc[j] += lo + hi;
        }
        __syncwarp();
    }

    // pack A row (lane owns row `lane` of C) into 16 b64 registers
    u64 arow[16];
#pragma unroll
    for (int i = 0; i < 16; i++) arow[i] = pk2(acc[2 * i], acc[2 * i + 1]);

    // ------------------------------------------------------------------
    // 2) Householder tridiagonalization, A-row in registers.
    //    Column k is read from row k (symmetry): lane k spills its row.
    // ------------------------------------------------------------------
    for (int k = 0; k < NA - 2; k++) {
        if (lane == k) {
#pragma unroll
            for (int i = 0; i < 16; i++) sts_u64(col_base + i * 8, arow[i]);
        }
        __syncwarp();

        float xr = scol[w][lane];                       // A[k][lane]
        float dk = __shfl_sync(0xffffffffu, xr, k);     // A[k][k]
        float x0 = __shfl_sync(0xffffffffu, xr, k + 1); // A[k][k+1]
        float sig = (lane > k + 1) ? xr * xr : 0.f;
#pragma unroll
        for (int o = 16; o; o >>= 1) sig += __shfl_xor_sync(0xffffffffu, sig, o);

        float alpha, vr = 0.f, beta = 0.f;
        if (sig < 1e-30f) {
            alpha = x0;
        } else {
            float mu = sqrtf(x0 * x0 + sig);
            alpha = (x0 > 0.f) ? -mu : mu;
            float v0 = x0 - alpha;
            vr = (lane == k + 1) ? v0 : ((lane > k + 1) ? xr : 0.f);
            beta = 2.f / (v0 * v0 + sig);
        }
        if (lane == 0) { d[k] = dk; e2[k + 1] = alpha * alpha; }
        sv[w][lane] = vr;                               // zero for lane <= k
        __syncwarp();

        if (beta > 0.f) {                               // uniform branch
            // p = beta * A v  (v zero-padded below k+1 -> full packed loop)
            u64 p2 = 0;
#pragma unroll
            for (int i = 0; i < 16; i++)
                p2 = ffma2(arow[i], lds_u64(v_base + i * 8), p2);
            float plo, phi; upk2(p2, plo, phi);
            float p = (plo + phi) * beta;

            float pv = p * vr;                          // vr=0 for lane<=k -> safe
#pragma unroll
            for (int o = 16; o; o >>= 1) pv += __shfl_xor_sync(0xffffffffu, pv, o);
            float K  = 0.5f * beta * pv;
            float wr = (lane > k) ? (p - K * vr) : 0.f;
            sw[w][lane] = wr;
            __syncwarp();

            // A -= v w^T + w v^T   (no-op for rows/cols <= k by zero padding)
            u64 nv = pk2(-vr, -vr);
            u64 nw = pk2(-wr, -wr);
#pragma unroll
            for (int i = 0; i < 16; i++) {
                u64 v2 = lds_u64(v_base + i * 8);
                u64 w2 = lds_u64(w_base + i * 8);
                arow[i] = ffma2(nv, w2, ffma2(nw, v2, arow[i]));
            }
        }
        __syncwarp();
    }

    if (lane == NA - 2) {                 // row 30: pair 15 = (A[30][30], A[30][31])
        float a, b; upk2(arow[15], a, b);
        d[NA - 2] = a;
    }
    if (lane == NA - 1) {                 // row 31: pair 15 = (A[31][30], A[31][31])
        float a, b; upk2(arow[15], a, b);
        d[NA - 1] = b;
        e2[NA - 1] = a * a;
    }
    if (lane == 0) e2[0] = 0.f;
    __syncwarp();

    // ------------------------------------------------------------------
    // 3) lambda_min: Gershgorin bracket + 32-way multisection (Sturm count)
    // ------------------------------------------------------------------
    float ei  = sqrtf(e2[lane]);
    float eip = (lane < NA - 1) ? sqrtf(e2[lane + 1]) : 0.f;
    float rad = ei + eip;
    float dl  = d[lane];
    float lo = dl - rad, hi = dl + rad;
#pragma unroll
    for (int o = 16; o; o >>= 1) {
        lo = fminf(lo, __shfl_xor_sync(0xffffffffu, lo, o));
        hi = fmaxf(hi, __shfl_xor_sync(0xffffffffu, hi, o));
    }

    for (int it = 0; it < 5; it++) {
        float step = (hi - lo) * (1.f / 33.f);
        float x = lo + step * (float)(lane + 1);
        int cnt = 0;
        float q = d[0] - x;
        if (q < 0.f) cnt++;
#pragma unroll 8
        for (int i = 1; i < NA; i++) {
            if (fabsf(q) < 1e-25f) q = (q < 0.f) ? -1e-25f : 1e-25f;
            q = (d[i] - x) - e2[i] / q;
            if (q < 0.f) cnt++;
        }
        unsigned mask = __ballot_sync(0xffffffffu, cnt >= 1);
        if (mask == 0u) {
            lo = lo + step * 32.f;
        } else {
            int idx = __ffs(mask) - 1;
            hi = lo + step * (float)(idx + 1);
            lo = lo + step * (float)idx;
        }
    }

    if (lane == 0) out[mol] = 0.5f * (lo + hi);
}

extern "C" void kernel_launch(void* const* d_in, const int* in_sizes, int n_in,
                              void* d_out, int out_size) {
    const float* sr = (const float*)d_in[0];   // [M*32, 128] fp32
    // d_in[1] = idx_m (int32) — uniform groups, unused
    float* out = (float*)d_out;

    int n_atoms = in_sizes[0] / NF;
    int mtot    = n_atoms / NA;

    int blocks = (mtot + WPB - 1) / WPB;
    corr_minEig_kernel<<<blocks, 32 * WPB>>>(sr, out, mtot);
}

// round 9
// speedup vs baseline: 3.1821x; 1.3728x over previous
#include <cuda_runtime.h>
#include <cuda_bf16.h>
#include <cstdint>

// Per molecule: S = 32x128 fp32, C = S S^T (32x32), output lambda_min(C).
// One warp per molecule:
//   1) Gram via SMEM-staged 32x32 chunks, packed f32x2 FMA (FFMA2)
//   2) Householder tridiagonalization, A-row in registers; column k is read
//      from the lane's OWN row by symmetry (k fully unrolled -> const index),
//      no spill, no per-step smem roundtrip for the column.
//   3) lambda_min via 32-way multisection on the Sturm sequence (approx div).

#define NA 32
#define NF 128
#define WPB 4   // warps (=molecules) per block

typedef unsigned long long u64;

__device__ __forceinline__ u64 pk2(float x, float y) {
    u64 r; asm("mov.b64 %0, {%1,%2};" : "=l"(r) : "f"(x), "f"(y)); return r;
}
__device__ __forceinline__ void upk2(u64 v, float& x, float& y) {
    asm("mov.b64 {%0,%1}, %2;" : "=f"(x), "=f"(y) : "l"(v));
}
__device__ __forceinline__ u64 ffma2(u64 a, u64 b, u64 c) {
    u64 d; asm("fma.rn.f32x2 %0, %1, %2, %3;" : "=l"(d) : "l"(a), "l"(b), "l"(c)); return d;
}
__device__ __forceinline__ u64 fadd2(u64 a, u64 b) {
    u64 d; asm("add.rn.f32x2 %0, %1, %2;" : "=l"(d) : "l"(a), "l"(b)); return d;
}
__device__ __forceinline__ void lds_v2u64(uint32_t addr, u64& a, u64& b) {
    asm("ld.shared.v2.b64 {%0,%1}, [%2];" : "=l"(a), "=l"(b) : "r"(addr));
}
__device__ __forceinline__ u64 lds_u64(uint32_t addr) {
    u64 a; asm("ld.shared.b64 %0, [%1];" : "=l"(a) : "r"(addr)); return a;
}

__global__ void __launch_bounds__(32 * WPB, 5)
corr_minEig_kernel(const float* __restrict__ S, float* __restrict__ out, int mtot) {
    __shared__ __align__(16) float sS[WPB][NA * 36];   // 32x32 chunk staging, stride 36
    __shared__ __align__(16) float sv[WPB][NA];        // Householder v
    __shared__ __align__(16) float sw[WPB][NA];        // Householder w
    __shared__ float sd[WPB][NA];                      // tridiagonal diag
    __shared__ float se2[WPB][NA];                     // tridiagonal offdiag^2

    const int w    = threadIdx.x >> 5;
    const int lane = threadIdx.x & 31;
    const int mol  = blockIdx.x * WPB + w;
    if (mol >= mtot) return;

    const float* Sm = S + (size_t)mol * NA * NF;
    const uint32_t sS_base = (uint32_t)__cvta_generic_to_shared(&sS[w][0]);
    const uint32_t v_base  = (uint32_t)__cvta_generic_to_shared(&sv[w][0]);
    const uint32_t w_base  = (uint32_t)__cvta_generic_to_shared(&sw[w][0]);
    float* d  = sd[w];
    float* e2 = se2[w];

    // ------------------------------------------------------------------
    // 1) Gram: acc[j] = dot(row lane, row j), chunked over k, packed FMA
    // ------------------------------------------------------------------
    float acc[NA];
#pragma unroll
    for (int j = 0; j < NA; j++) acc[j] = 0.f;

    for (int kc = 0; kc < NF; kc += 32) {
        // stage 32x32 chunk (coalesced 128B segments)
#pragma unroll
        for (int it = 0; it < 8; it++) {
            int p   = it * 32 + lane;
            int row = p >> 3;
            int c4  = p & 7;
            float4 x = *(const float4*)(Sm + row * NF + kc + c4 * 4);
            *(float4*)(&sS[w][row * 36 + c4 * 4]) = x;
        }
        __syncwarp();

        // own row chunk -> 16 packed b64 (conflict-free)
        u64 a2[16];
#pragma unroll
        for (int c4 = 0; c4 < 8; c4++)
            lds_v2u64(sS_base + (uint32_t)(lane * 36 + c4 * 4) * 4, a2[2 * c4], a2[2 * c4 + 1]);

#pragma unroll
        for (int j = 0; j < NA; j++) {
            u64 s01 = 0, s23 = 0;
#pragma unroll
            for (int c4 = 0; c4 < 8; c4++) {
                u64 b01, b23;   // broadcast load
                lds_v2u64(sS_base + (uint32_t)(j * 36 + c4 * 4) * 4, b01, b23);
                s01 = ffma2(a2[2 * c4],     b01, s01);
                s23 = ffma2(a2[2 * c4 + 1], b23, s23);
            }
            u64 s = fadd2(s01, s23);
            float lo, hi; upk2(s, lo, hi);
            acc[j] += lo + hi;
        }
        __syncwarp();
    }

    // pack A row (lane owns row `lane` of C) into 16 b64 registers
    u64 arow[16];
#pragma unroll
    for (int i = 0; i < 16; i++) arow[i] = pk2(acc[2 * i], acc[2 * i + 1]);

    // ------------------------------------------------------------------
    // 2) Householder tridiagonalization, fully unrolled over k.
    //    Column k is element k of the lane's own row (symmetry) ->
    //    constant register index, no spill.
    // ------------------------------------------------------------------
#pragma unroll
    for (int k = 0; k < NA - 2; k++) {
        const int i0 = k >> 1;      // first pair touching columns > k-1

        float ea, eb; upk2(arow[k >> 1], ea, eb);
        float xr = (k & 1) ? eb : ea;                    // A[lane][k] == A[k][lane]
        float dk = __shfl_sync(0xffffffffu, xr, k);      // A[k][k]
        float x0 = __shfl_sync(0xffffffffu, xr, k + 1);  // A[k][k+1]
        float sig = (lane > k + 1) ? xr * xr : 0.f;
#pragma unroll
        for (int o = 16; o; o >>= 1) sig += __shfl_xor_sync(0xffffffffu, sig, o);

        float alpha, vr = 0.f, beta = 0.f;
        if (sig < 1e-30f) {
            alpha = x0;
        } else {
            float mu = sqrtf(x0 * x0 + sig);
            alpha = (x0 > 0.f) ? -mu : mu;
            float v0 = x0 - alpha;
            vr = (lane == k + 1) ? v0 : ((lane > k + 1) ? xr : 0.f);
            beta = 2.f / (v0 * v0 + sig);
        }
        if (lane == 0) { d[k] = dk; e2[k + 1] = alpha * alpha; }
        sv[w][lane] = vr;                                // zero for lane <= k
        __syncwarp();

        if (beta > 0.f) {                                // uniform branch
            // v pairs into registers (reused in p-loop and update)
            u64 v2[16];
#pragma unroll
            for (int i = i0; i < 16; i++) v2[i] = lds_u64(v_base + i * 8);

            // p = beta * A v  (v zero-padded below k+1)
            u64 p2 = 0;
#pragma unroll
            for (int i = i0; i < 16; i++) p2 = ffma2(arow[i], v2[i], p2);
            float plo, phi; upk2(p2, plo, phi);
            float p = (plo + phi) * beta;

            float pv = p * vr;                           // vr=0 for lane<=k
#pragma unroll
            for (int o = 16; o; o >>= 1) pv += __shfl_xor_sync(0xffffffffu, pv, o);
            float K  = 0.5f * beta * pv;
            float wr = (lane > k) ? (p - K * vr) : 0.f;
            sw[w][lane] = wr;
            __syncwarp();

            // A -= v w^T + w v^T (untouched pairs below i0 skipped)
            u64 nv = pk2(-vr, -vr);
            u64 nw = pk2(-wr, -wr);
#pragma unroll
            for (int i = i0; i < 16; i++)
                arow[i] = ffma2(nv, lds_u64(w_base + i * 8), ffma2(nw, v2[i], arow[i]));
        }
        __syncwarp();
    }

    if (lane == NA - 2) {                 // row 30: pair 15 = (A[30][30], A[30][31])
        float a, b; upk2(arow[15], a, b);
        d[NA - 2] = a;
    }
    if (lane == NA - 1) {                 // row 31: pair 15 = (A[31][30], A[31][31])
        float a, b; upk2(arow[15], a, b);
        d[NA - 1] = b;
        e2[NA - 1] = a * a;
    }
    if (lane == 0) e2[0] = 0.f;
    __syncwarp();

    // ------------------------------------------------------------------
    // 3) lambda_min: Gershgorin bracket + 32-way multisection (Sturm count)
    // ------------------------------------------------------------------
    float ei  = sqrtf(e2[lane]);
    float eip = (lane < NA - 1) ? sqrtf(e2[lane + 1]) : 0.f;
    float rad = ei + eip;
    float dl  = d[lane];
    float lo = dl - rad, hi = dl + rad;
#pragma unroll
    for (int o = 16; o; o >>= 1) {
        lo = fminf(lo, __shfl_xor_sync(0xffffffffu, lo, o));
        hi = fmaxf(hi, __shfl_xor_sync(0xffffffffu, hi, o));
    }

    for (int it = 0; it < 5; it++) {
        float step = (hi - lo) * (1.f / 33.f);
        float x = lo + step * (float)(lane + 1);
        int cnt = 0;
        float q = d[0] - x;
        if (q < 0.f) cnt++;
#pragma unroll
        for (int i = 1; i < NA; i++) {
            if (fabsf(q) < 1e-25f) q = (q < 0.f) ? -1e-25f : 1e-25f;
            q = (d[i] - x) - __fdividef(e2[i], q);
            if (q < 0.f) cnt++;
        }
        unsigned mask = __ballot_sync(0xffffffffu, cnt >= 1);
        if (mask == 0u) {
            lo = lo + step * 32.f;
        } else {
            int idx = __ffs(mask) - 1;
            hi = lo + step * (float)(idx + 1);
            lo = lo + step * (float)idx;
        }
    }

    if (lane == 0) out[mol] = 0.5f * (lo + hi);
}

extern "C" void kernel_launch(void* const* d_in, const int* in_sizes, int n_in,
                              void* d_out, int out_size) {
    const float* sr = (const float*)d_in[0];   // [M*32, 128] fp32
    // d_in[1] = idx_m (int32) — uniform groups, unused
    float* out = (float*)d_out;

    int n_atoms = in_sizes[0] / NF;
    int mtot    = n_atoms / NA;

    int blocks = (mtot + WPB - 1) / WPB;
    corr_minEig_kernel<<<blocks, 32 * WPB>>>(sr, out, mtot);
}

// round 10
// speedup vs baseline: 3.4061x; 1.0704x over previous
#include <cuda_runtime.h>
#include <cuda_bf16.h>
#include <cstdint>

// Per molecule: S = 32x128 fp32, C = S S^T (32x32), output lambda_min(C).
// One warp per molecule:
//   1) Gram via SMEM-staged 32x32 chunks, SYMMETRIC diagonal-wrap (t=0..16),
//      packed f32x2 FMA; full rows reconstructed once via smem scatter.
//   2) Householder tridiagonalization, A-row in registers; column k read from
//      the lane's own row by symmetry (fully unrolled -> const reg index).
//   3) lambda_min via 32-way multisection on the Sturm sequence (4 rounds).

#define NA 32
#define NF 128
#define WPB 4   // warps (=molecules) per block

typedef unsigned long long u64;

__device__ __forceinline__ u64 pk2(float x, float y) {
    u64 r; asm("mov.b64 %0, {%1,%2};" : "=l"(r) : "f"(x), "f"(y)); return r;
}
__device__ __forceinline__ void upk2(u64 v, float& x, float& y) {
    asm("mov.b64 {%0,%1}, %2;" : "=f"(x), "=f"(y) : "l"(v));
}
__device__ __forceinline__ u64 ffma2(u64 a, u64 b, u64 c) {
    u64 d; asm("fma.rn.f32x2 %0, %1, %2, %3;" : "=l"(d) : "l"(a), "l"(b), "l"(c)); return d;
}
__device__ __forceinline__ u64 fadd2(u64 a, u64 b) {
    u64 d; asm("add.rn.f32x2 %0, %1, %2;" : "=l"(d) : "l"(a), "l"(b)); return d;
}
__device__ __forceinline__ void lds_v2u64(uint32_t addr, u64& a, u64& b) {
    asm("ld.shared.v2.b64 {%0,%1}, [%2];" : "=l"(a), "=l"(b) : "r"(addr));
}
__device__ __forceinline__ u64 lds_u64(uint32_t addr) {
    u64 a; asm("ld.shared.b64 %0, [%1];" : "=l"(a) : "r"(addr)); return a;
}

__global__ void __launch_bounds__(32 * WPB, 6)
corr_minEig_kernel(const float* __restrict__ S, float* __restrict__ out, int mtot) {
    // sS: 32x32 chunk staging (stride 36); reused post-Gram as C (stride 34)
    __shared__ __align__(16) float sS[WPB][NA * 36];
    __shared__ __align__(16) float sv[WPB][NA];        // Householder v
    __shared__ __align__(16) float sw[WPB][NA];        // Householder w
    __shared__ float sd[WPB][NA];                      // tridiagonal diag
    __shared__ float se2[WPB][NA];                     // tridiagonal offdiag^2

    const int w    = threadIdx.x >> 5;
    const int lane = threadIdx.x & 31;
    const int mol  = blockIdx.x * WPB + w;
    if (mol >= mtot) return;

    const float* Sm = S + (size_t)mol * NA * NF;
    const uint32_t sS_base = (uint32_t)__cvta_generic_to_shared(&sS[w][0]);
    const uint32_t v_base  = (uint32_t)__cvta_generic_to_shared(&sv[w][0]);
    const uint32_t w_base  = (uint32_t)__cvta_generic_to_shared(&sw[w][0]);
    float* d  = sd[w];
    float* e2 = se2[w];

    // ------------------------------------------------------------------
    // 1) Symmetric Gram: acc_t[t] = dot(row lane, row (lane+t)&31), t=0..16
    // ------------------------------------------------------------------
    float acc_t[17];
#pragma unroll
    for (int t = 0; t <= 16; t++) acc_t[t] = 0.f;

    for (int kc = 0; kc < NF; kc += 32) {
        // stage 32x32 chunk (coalesced 128B segments)
#pragma unroll
        for (int it = 0; it < 8; it++) {
            int p   = it * 32 + lane;
            int row = p >> 3;
            int c4  = p & 7;
            float4 x = *(const float4*)(Sm + row * NF + kc + c4 * 4);
            *(float4*)(&sS[w][row * 36 + c4 * 4]) = x;
        }
        __syncwarp();

        // own row chunk -> 16 packed b64 (conflict-free)
        u64 a2[16];
#pragma unroll
        for (int c4 = 0; c4 < 8; c4++)
            lds_v2u64(sS_base + (uint32_t)(lane * 36 + c4 * 4) * 4, a2[2 * c4], a2[2 * c4 + 1]);

        // t = 0: self dot (no reload)
        {
            u64 s01 = 0, s23 = 0;
#pragma unroll
            for (int c4 = 0; c4 < 8; c4++) {
                s01 = ffma2(a2[2 * c4],     a2[2 * c4],     s01);
                s23 = ffma2(a2[2 * c4 + 1], a2[2 * c4 + 1], s23);
            }
            float lo, hi; upk2(fadd2(s01, s23), lo, hi);
            acc_t[0] += lo + hi;
        }
        // t = 1..16: rotated partner row (rows distinct mod 8 across any
        // 8 consecutive lanes at stride 36 -> conflict-free LDS.128)
#pragma unroll
        for (int t = 1; t <= 16; t++) {
            int r = (lane + t) & 31;
            uint32_t raddr = sS_base + (uint32_t)r * 144u;
            u64 s01 = 0, s23 = 0;
#pragma unroll
            for (int c4 = 0; c4 < 8; c4++) {
                u64 b01, b23;
                lds_v2u64(raddr + c4 * 16u, b01, b23);
                s01 = ffma2(a2[2 * c4],     b01, s01);
                s23 = ffma2(a2[2 * c4 + 1], b23, s23);
            }
            float lo, hi; upk2(fadd2(s01, s23), lo, hi);
            acc_t[t] += lo + hi;
        }
        __syncwarp();
    }

    // Reconstruct full rows: scatter into C (stride 34, reusing sS space)
    float* C = sS[w];
#pragma unroll
    for (int t = 0; t <= 16; t++) {
        int j = (lane + t) & 31;
        C[lane * 34 + j] = acc_t[t];
        if (t != 0 && t != 16) C[j * 34 + lane] = acc_t[t];
        // t=16: lane l writes C[l][l+16], lane l+16 writes C[l+16][l] -> covered
    }
    __syncwarp();

    u64 arow[16];
#pragma unroll
    for (int i = 0; i < 16; i++)
        arow[i] = lds_u64(sS_base + (uint32_t)(lane * 34 + 2 * i) * 4);
    __syncwarp();

    // ------------------------------------------------------------------
    // 2) Householder tridiagonalization, fully unrolled over k.
    //    Column k == element k of the lane's own row (symmetry).
    // ------------------------------------------------------------------
#pragma unroll
    for (int k = 0; k < NA - 2; k++) {
        const int i0 = k >> 1;      // first pair touching columns > k-1

        float ea, eb; upk2(arow[k >> 1], ea, eb);
        float xr = (k & 1) ? eb : ea;                    // A[lane][k] == A[k][lane]
        float dk = __shfl_sync(0xffffffffu, xr, k);      // A[k][k]
        float x0 = __shfl_sync(0xffffffffu, xr, k + 1);  // A[k][k+1]
        float sig = (lane > k + 1) ? xr * xr : 0.f;
#pragma unroll
        for (int o = 16; o; o >>= 1) sig += __shfl_xor_sync(0xffffffffu, sig, o);

        float alpha, vr = 0.f, beta = 0.f;
        if (sig < 1e-30f) {
            alpha = x0;
        } else {
            float mu = sqrtf(x0 * x0 + sig);
            alpha = (x0 > 0.f) ? -mu : mu;
            float v0 = x0 - alpha;
            vr = (lane == k + 1) ? v0 : ((lane > k + 1) ? xr : 0.f);
            beta = 2.f / (v0 * v0 + sig);
        }
        if (lane == 0) { d[k] = dk; e2[k + 1] = alpha * alpha; }
        sv[w][lane] = vr;                                // zero for lane <= k
        __syncwarp();

        if (beta > 0.f) {                                // uniform branch
            // p = beta * A v  (v zero-padded below k+1)
            u64 p2 = 0;
#pragma unroll
            for (int i = i0; i < 16; i++)
                p2 = ffma2(arow[i], lds_u64(v_base + i * 8), p2);
            float plo, phi; upk2(p2, plo, phi);
            float p = (plo + phi) * beta;

            float pv = p * vr;                           // vr=0 for lane<=k
#pragma unroll
            for (int o = 16; o; o >>= 1) pv += __shfl_xor_sync(0xffffffffu, pv, o);
            float K  = 0.5f * beta * pv;
            float wr = (lane > k) ? (p - K * vr) : 0.f;
            sw[w][lane] = wr;
            __syncwarp();

            // A -= v w^T + w v^T (interleaved loads keep live regs low)
            u64 nv = pk2(-vr, -vr);
            u64 nw = pk2(-wr, -wr);
#pragma unroll
            for (int i = i0; i < 16; i++) {
                u64 v2 = lds_u64(v_base + i * 8);
                u64 w2 = lds_u64(w_base + i * 8);
                arow[i] = ffma2(nv, w2, ffma2(nw, v2, arow[i]));
            }
        }
        __syncwarp();
    }

    if (lane == NA - 2) {                 // row 30: pair 15 = (A[30][30], A[30][31])
        float a, b; upk2(arow[15], a, b);
        d[NA - 2] = a;
    }
    if (lane == NA - 1) {                 // row 31: pair 15 = (A[31][30], A[31][31])
        float a, b; upk2(arow[15], a, b);
        d[NA - 1] = b;
        e2[NA - 1] = a * a;
    }
    if (lane == 0) e2[0] = 0.f;
    __syncwarp();

    // ------------------------------------------------------------------
    // 3) lambda_min: Gershgorin bracket + 32-way multisection (Sturm count)
    // ------------------------------------------------------------------
    float ei  = sqrtf(e2[lane]);
    float eip = (lane < NA - 1) ? sqrtf(e2[lane + 1]) : 0.f;
    float rad = ei + eip;
    float dl  = d[lane];
    float lo = dl - rad, hi = dl + rad;
#pragma unroll
    for (int o = 16; o; o >>= 1) {
        lo = fminf(lo, __shfl_xor_sync(0xffffffffu, lo, o));
        hi = fmaxf(hi, __shfl_xor_sync(0xffffffffu, hi, o));
    }

    for (int it = 0; it < 4; it++) {
        float step = (hi - lo) * (1.f / 33.f);
        float x = lo + step * (float)(lane + 1);
        int cnt = 0;
        float q = d[0] - x;
        if (q < 0.f) cnt++;
#pragma unroll
        for (int i = 1; i < NA; i++) {
            if (fabsf(q) < 1e-25f) q = (q < 0.f) ? -1e-25f : 1e-25f;
            q = (d[i] - x) - __fdividef(e2[i], q);
            if (q < 0.f) cnt++;
        }
        unsigned mask = __ballot_sync(0xffffffffu, cnt >= 1);
        if (mask == 0u) {
            lo = lo + step * 32.f;
        } else {
            int idx = __ffs(mask) - 1;
            hi = lo + step * (float)(idx + 1);
            lo = lo + step * (float)idx;
        }
    }

    if (lane == 0) out[mol] = 0.5f * (lo + hi);
}

extern "C" void kernel_launch(void* const* d_in, const int* in_sizes, int n_in,
                              void* d_out, int out_size) {
    const float* sr = (const float*)d_in[0];   // [M*32, 128] fp32
    // d_in[1] = idx_m (int32) — uniform groups, unused
    float* out = (float*)d_out;

    int n_atoms = in_sizes[0] / NF;
    int mtot    = n_atoms / NA;

    int blocks = (mtot + WPB - 1) / WPB;
    corr_minEig_kernel<<<blocks, 32 * WPB>>>(sr, out, mtot);
}